// round 5
// baseline (speedup 1.0000x reference)
#include <cuda_runtime.h>
#include <cuda_bf16.h>

// PitchLoss: reference's (N,B,L) broadcast collapses analytically because
// mask[n,b,l] = c[b,n] is constant over l:
//   diff[b,n] = | c[b,n] * (mean_g[b] - mean_t[b]) / (c[b,n] + 1e-6) |
//   loss      = mean_{b,n} relu(diff - 0.5)
// with c[b,n] = -(# onsets at idx>=1 in segment n) - (n==0 ? offsets[b,0] : 0),
// zeroed for n >= n_notes[b]; segment index = inclusive cumsum of offsets.
//
// R5 change: cp.async (LDGSTS) staging of all 4 input rows into smem.
// LDGSTS has no destination register, so ptxas cannot serialize the load
// chain (R3/R4 showed regs pinned at 38 -> MLP collapsed, DRAM 6% busy).
// All 16 copies per thread are in flight at once; each thread stages only
// the chunks it reads back, so no block barrier is needed after wait.

#define BATCH 64
#define LEN   4096
#define NMAX  128
#define T1    256
#define CHUNK (LEN / T1)   // 16 elements / thread
#define NV    (CHUNK / 4)  // 4 x 16B chunks per array per thread
#define FULLM 0xffffffffu
#define STAGE_BYTES (4 * LEN * 4)   // 64 KB: g, t, onsets, offsets rows

__device__ float g_partial[BATCH];
__device__ int   g_ticket = 0;

__device__ __forceinline__ void cp16(void* smem_dst, const void* gsrc)
{
    unsigned s = (unsigned)__cvta_generic_to_shared(smem_dst);
    asm volatile("cp.async.cg.shared.global [%0], [%1], 16;\n" :: "r"(s), "l"(gsrc));
}

__global__ __launch_bounds__(T1)
void pitch_fused_kernel(const float* __restrict__ gen_f0,
                        const float* __restrict__ contours,
                        const int*   __restrict__ onsets,
                        const int*   __restrict__ offsets,
                        float*       __restrict__ out)
{
    const int b    = blockIdx.x;
    const int tid  = threadIdx.x;
    const int lane = tid & 31;
    const int wid  = tid >> 5;           // 8 warps

    extern __shared__ unsigned char sraw[];
    float4* sh_g  = (float4*)(sraw);
    float4* sh_t  = (float4*)(sraw + LEN * 4);
    int4*   sh_on = (int4*)(sraw + 2 * LEN * 4);
    int4*   sh_of = (int4*)(sraw + 3 * LEN * 4);

    const float4* gr  = (const float4*)(gen_f0   + (size_t)b * LEN)     + tid * NV;
    const float4* tr  = (const float4*)(contours + (size_t)b * 2 * LEN) + tid * NV;
    const int4*   on  = (const int4*)(onsets  + (size_t)b * LEN) + tid * NV;
    const int4*   off = (const int4*)(offsets + (size_t)b * LEN) + tid * NV;

    __shared__ int   s_counts[NMAX];
    __shared__ int   s_wosum[8];
    __shared__ float s_wg[8], s_wt[8];
    __shared__ float s_red[4];
    __shared__ int   s_off0;
    __shared__ int   s_islast;

    // ---- stage all inputs via cp.async: 16 LDGSTS in flight, no reg pressure ----
#pragma unroll
    for (int j = 0; j < NV; j++) cp16(&sh_g [tid * NV + j], &gr [j]);
#pragma unroll
    for (int j = 0; j < NV; j++) cp16(&sh_t [tid * NV + j], &tr [j]);
#pragma unroll
    for (int j = 0; j < NV; j++) cp16(&sh_of[tid * NV + j], &off[j]);
#pragma unroll
    for (int j = 0; j < NV; j++) cp16(&sh_on[tid * NV + j], &on [j]);
    asm volatile("cp.async.commit_group;\n" ::: "memory");

    if (tid < NMAX) s_counts[tid] = 0;   // overlaps with copy latency

    asm volatile("cp.async.wait_group 0;\n" ::: "memory");
    // each thread reads back only its own staged chunks -> no __syncthreads here

    // ---- sums + 16-bit on/off masks (LDS hits) ----
    float sg = 0.f, st = 0.f;
    unsigned offm = 0, onm = 0;
#pragma unroll
    for (int j = 0; j < NV; j++) {
        float4 g4 = sh_g [tid * NV + j];
        float4 t4 = sh_t [tid * NV + j];
        int4   o4 = sh_of[tid * NV + j];
        int4   n4 = sh_on[tid * NV + j];
        sg += (g4.x + g4.y) + (g4.z + g4.w);
        st += (t4.x + t4.y) + (t4.z + t4.w);
        const int s = 4 * j;
        offm |= ((unsigned)o4.x << s) | ((unsigned)o4.y << (s + 1))
              | ((unsigned)o4.z << (s + 2)) | ((unsigned)o4.w << (s + 3));
        onm  |= ((unsigned)n4.x << s) | ((unsigned)n4.y << (s + 1))
              | ((unsigned)n4.z << (s + 2)) | ((unsigned)n4.w << (s + 3));
    }
    const int osum = __popc(offm);

    // ---- warp-level: inclusive scan of osum, reduce sg/st ----
    int incl = osum;
#pragma unroll
    for (int d = 1; d < 32; d <<= 1) {
        int v = __shfl_up_sync(FULLM, incl, d);
        if (lane >= d) incl += v;
    }
#pragma unroll
    for (int d = 16; d > 0; d >>= 1) {
        sg += __shfl_down_sync(FULLM, sg, d);
        st += __shfl_down_sync(FULLM, st, d);
    }
    if (lane == 31) s_wosum[wid] = incl;
    if (lane == 0) { s_wg[wid] = sg; s_wt[wid] = st; }
    if (tid == 0) s_off0 = (int)(offm & 1u);
    __syncthreads();

    // ---- cross-warp prefix + scatter onset counts ----
    int wpre = 0;
#pragma unroll
    for (int w = 0; w < 8; w++) wpre += (w < wid) ? s_wosum[w] : 0;
    const int excl = wpre + incl - osum;   // exclusive prefix of this thread

    unsigned m = onm;
    if (tid == 0) m &= ~1u;                // reference masks onsets at idx==0
    while (m) {
        const int j = __ffs(m) - 1;
        m &= m - 1;
        const int seg = excl + __popc(offm & ((2u << j) - 1u));  // inclusive cumsum at l
        if (seg < NMAX) atomicAdd(&s_counts[seg], 1);
    }
    __syncthreads();

    // ---- per-note loss, block reduce ----
    int   n_notes = 0;
    float tg = 0.f, tt = 0.f;
#pragma unroll
    for (int w = 0; w < 8; w++) { n_notes += s_wosum[w]; tg += s_wg[w]; tt += s_wt[w]; }
    const float dd = (tg - tt) * (1.0f / LEN);

    float val = 0.f;
    if (tid < NMAX) {
        float c = -(float)s_counts[tid];
        if (tid == 0) c -= (float)s_off0;
        if (tid >= n_notes) c = 0.f;
        const float diff = fabsf(c * dd / (c + 1e-6f));
        val = fmaxf(diff - 0.5f, 0.f);
    }
#pragma unroll
    for (int d = 16; d > 0; d >>= 1) val += __shfl_down_sync(FULLM, val, d);
    if (lane == 0 && wid < 4) s_red[wid] = val;   // warps 0-3 hold tid<128
    __syncthreads();

    if (tid == 0) {
        g_partial[b] = (s_red[0] + s_red[1]) + (s_red[2] + s_red[3]);
        __threadfence();
        const int old = atomicAdd(&g_ticket, 1);
        s_islast = (old == BATCH - 1);   // no spin: only last arrival proceeds
    }
    __syncthreads();

    // ---- last block: reduce 64 partials, write output, rearm ticket ----
    if (s_islast) {
        float v = (tid < BATCH) ? g_partial[tid] : 0.f;
#pragma unroll
        for (int d = 16; d > 0; d >>= 1) v += __shfl_down_sync(FULLM, v, d);
        if (lane == 0 && wid < 2) s_red[wid] = v;
        __syncthreads();
        if (tid == 0) {
            out[0] = (s_red[0] + s_red[1]) * (1.0f / (NMAX * BATCH));
            g_ticket = 0;   // rearm for next graph replay
        }
    }
}

extern "C" void kernel_launch(void* const* d_in, const int* in_sizes, int n_in,
                              void* d_out, int out_size)
{
    const float* gen_f0   = (const float*)d_in[0];
    const float* contours = (const float*)d_in[1];
    const int*   onsets   = (const int*)d_in[2];
    const int*   offsets  = (const int*)d_in[3];
    // d_in[4] = n_notes_max (compile-time NMAX=128 for this shape)

    // idempotent; not a stream op, safe under graph capture
    cudaFuncSetAttribute(pitch_fused_kernel,
                         cudaFuncAttributeMaxDynamicSharedMemorySize, STAGE_BYTES);

    pitch_fused_kernel<<<BATCH, T1, STAGE_BYTES>>>(gen_f0, contours, onsets, offsets,
                                                   (float*)d_out);
}

// round 6
// speedup vs baseline: 1.0390x; 1.0390x over previous
#include <cuda_runtime.h>
#include <cuda_bf16.h>

// PitchLoss: reference's (N,B,L) broadcast collapses analytically because
// mask[n,b,l] = c[b,n] is constant over l:
//   diff[b,n] = | c[b,n] * (mean_g[b] - mean_t[b]) / (c[b,n] + 1e-6) |
//   loss      = mean_{b,n} relu(diff - 0.5)
// with c[b,n] = -(# onsets at idx>=1 in segment n) - (n==0 ? offsets[b,0] : 0),
// zeroed for n >= n_notes[b]; segment index = inclusive cumsum of offsets.
//
// R6: revert cp.async (neutral on kernel time, regressed wall time via
// dynamic-smem launch overhead). Instead: 1024 threads/block, 4 elem/thread,
// exactly ONE vectorized load per input array per thread -> 4 independent
// LDG.128s that cannot be serialized by ptxas, and 32 warps/block (8/SMSP)
// to hide the single exposed DRAM latency. Ticket-based fused final reduce.

#define BATCH 64
#define LEN   4096
#define NMAX  128
#define T1    1024
#define NW    (T1 / 32)    // 32 warps
#define FULLM 0xffffffffu

__device__ float g_partial[BATCH];
__device__ int   g_ticket = 0;

__global__ __launch_bounds__(T1)
void pitch_fused_kernel(const float* __restrict__ gen_f0,
                        const float* __restrict__ contours,
                        const int*   __restrict__ onsets,
                        const int*   __restrict__ offsets,
                        float*       __restrict__ out)
{
    const int b    = blockIdx.x;
    const int tid  = threadIdx.x;
    const int lane = tid & 31;
    const int wid  = tid >> 5;           // 0..31

    // one 16B chunk per array per thread
    const float4 g4 = ((const float4*)(gen_f0   + (size_t)b * LEN))[tid];
    const float4 t4 = ((const float4*)(contours + (size_t)b * 2 * LEN))[tid];
    const int4   o4 = ((const int4*)(offsets + (size_t)b * LEN))[tid];
    const int4   n4 = ((const int4*)(onsets  + (size_t)b * LEN))[tid];

    __shared__ int   s_counts[NMAX];
    __shared__ int   s_wosum[NW];
    __shared__ float s_wg[NW], s_wt[NW];
    __shared__ float s_red[4];
    __shared__ int   s_off0;
    __shared__ int   s_islast;

    if (tid < NMAX) s_counts[tid] = 0;

    // ---- per-thread sums + 4-bit on/off masks ----
    const float sg = (g4.x + g4.y) + (g4.z + g4.w);
    const float st = (t4.x + t4.y) + (t4.z + t4.w);
    const unsigned offm = ((unsigned)o4.x) | ((unsigned)o4.y << 1)
                        | ((unsigned)o4.z << 2) | ((unsigned)o4.w << 3);
    const unsigned onm  = ((unsigned)n4.x) | ((unsigned)n4.y << 1)
                        | ((unsigned)n4.z << 2) | ((unsigned)n4.w << 3);
    const int osum = __popc(offm);

    // ---- warp-level: inclusive scan of osum, reduce sg/st ----
    int incl = osum;
#pragma unroll
    for (int d = 1; d < 32; d <<= 1) {
        int v = __shfl_up_sync(FULLM, incl, d);
        if (lane >= d) incl += v;
    }
    float rg = sg, rt = st;
#pragma unroll
    for (int d = 16; d > 0; d >>= 1) {
        rg += __shfl_down_sync(FULLM, rg, d);
        rt += __shfl_down_sync(FULLM, rt, d);
    }
    if (lane == 31) s_wosum[wid] = incl;
    if (lane == 0) { s_wg[wid] = rg; s_wt[wid] = rt; }
    if (tid == 0) s_off0 = (int)(offm & 1u);
    __syncthreads();

    // ---- cross-warp prefix + scatter onset counts ----
    int wpre = 0;
#pragma unroll
    for (int w = 0; w < NW; w++) wpre += (w < wid) ? s_wosum[w] : 0;
    const int excl = wpre + incl - osum;   // exclusive offset-prefix of this thread

    unsigned m = onm;
    if (tid == 0) m &= ~1u;                // reference masks onsets at idx==0
    while (m) {
        const int j = __ffs(m) - 1;
        m &= m - 1;
        const int seg = excl + __popc(offm & ((2u << j) - 1u));  // inclusive cumsum at l
        if (seg < NMAX) atomicAdd(&s_counts[seg], 1);
    }
    __syncthreads();

    // ---- per-note loss, block reduce ----
    int   n_notes = 0;
    float tg = 0.f, tt = 0.f;
#pragma unroll
    for (int w = 0; w < NW; w++) { n_notes += s_wosum[w]; tg += s_wg[w]; tt += s_wt[w]; }
    const float dd = (tg - tt) * (1.0f / LEN);

    float val = 0.f;
    if (tid < NMAX) {
        float c = -(float)s_counts[tid];
        if (tid == 0) c -= (float)s_off0;
        if (tid >= n_notes) c = 0.f;
        const float diff = fabsf(c * dd / (c + 1e-6f));
        val = fmaxf(diff - 0.5f, 0.f);
    }
#pragma unroll
    for (int d = 16; d > 0; d >>= 1) val += __shfl_down_sync(FULLM, val, d);
    if (lane == 0 && wid < 4) s_red[wid] = val;   // warps 0-3 hold tid<128
    __syncthreads();

    if (tid == 0) {
        g_partial[b] = (s_red[0] + s_red[1]) + (s_red[2] + s_red[3]);
        __threadfence();
        const int old = atomicAdd(&g_ticket, 1);
        s_islast = (old == BATCH - 1);   // no spin: only last arrival proceeds
    }
    __syncthreads();

    // ---- last block: reduce 64 partials, write output, rearm ticket ----
    if (s_islast) {
        float v = (tid < BATCH) ? g_partial[tid] : 0.f;
#pragma unroll
        for (int d = 16; d > 0; d >>= 1) v += __shfl_down_sync(FULLM, v, d);
        if (lane == 0 && wid < 2) s_red[wid] = v;
        __syncthreads();
        if (tid == 0) {
            out[0] = (s_red[0] + s_red[1]) * (1.0f / (NMAX * BATCH));
            g_ticket = 0;   // rearm for next graph replay
        }
    }
}

extern "C" void kernel_launch(void* const* d_in, const int* in_sizes, int n_in,
                              void* d_out, int out_size)
{
    const float* gen_f0   = (const float*)d_in[0];
    const float* contours = (const float*)d_in[1];
    const int*   onsets   = (const int*)d_in[2];
    const int*   offsets  = (const int*)d_in[3];
    // d_in[4] = n_notes_max (compile-time NMAX=128 for this shape)

    pitch_fused_kernel<<<BATCH, T1>>>(gen_f0, contours, onsets, offsets, (float*)d_out);
}

// round 8
// speedup vs baseline: 1.2451x; 1.1984x over previous
#include <cuda_runtime.h>
#include <cuda_bf16.h>

// PitchLoss: reference's (N,B,L) broadcast collapses analytically because
// mask[n,b,l] = c[b,n] is constant over l:
//   diff[b,n] = | c[b,n] * (mean_g[b] - mean_t[b]) / (c[b,n] + 1e-6) |
//   loss      = mean_{b,n} relu(diff - 0.5)
// with c[b,n] = -(# onsets at idx>=1 in segment n) - (n==0 ? offsets[b,0] : 0),
// zeroed for n >= n_notes[b]; segment index = inclusive cumsum of offsets.
//
// R8 (= R7 resubmit after infra failure): R4/R6 showed kernel time invariant
// to body structure (occ 13%->46%, issue 8%->25%, same dur) -> bottleneck is
// the serialized global tail (STG partial + fence + ticket + cross-SM
// readback + reduce). Replace it with ONE packed 64-bit atomic:
// bits[57:64)=block count, bits[0:57)=fixed-point partial sum (relu output
// is >= 0, so no sign issues). The last arrival's atomicAdd return value IS
// the complete sum -> no threadfence, no partial array, no readback.
// Integer adds are commutative -> bit-deterministic across graph replays.

#define BATCH 64
#define LEN   4096
#define NMAX  128
#define T1    256
#define CHUNK (LEN / T1)   // 16 elements / thread
#define NV    (CHUNK / 4)
#define FULLM 0xffffffffu
#define CNT_SHIFT 57
#define VAL_MASK  ((1ULL << CNT_SHIFT) - 1ULL)
#define FP_SCALE  68719476736.0f   // 2^36

__device__ unsigned long long g_pack = 0ULL;

__global__ __launch_bounds__(T1)
void pitch_fused_kernel(const float* __restrict__ gen_f0,
                        const float* __restrict__ contours,
                        const int*   __restrict__ onsets,
                        const int*   __restrict__ offsets,
                        float*       __restrict__ out)
{
    const int b    = blockIdx.x;
    const int tid  = threadIdx.x;
    const int lane = tid & 31;
    const int wid  = tid >> 5;           // 8 warps

    const float4* __restrict__ gr  = (const float4*)(gen_f0   + (size_t)b * LEN)     + tid * NV;
    const float4* __restrict__ tr  = (const float4*)(contours + (size_t)b * 2 * LEN) + tid * NV;
    const int4*   __restrict__ on  = (const int4*)(onsets  + (size_t)b * LEN) + tid * NV;
    const int4*   __restrict__ off = (const int4*)(offsets + (size_t)b * LEN) + tid * NV;

    __shared__ int   s_counts[NMAX];
    __shared__ int   s_wosum[8];
    __shared__ float s_wg[8], s_wt[8];
    __shared__ float s_red[4];

    if (tid < NMAX) s_counts[tid] = 0;

    // ---- loads: sums + 16-bit on/off masks ----
    float sg = 0.f, st = 0.f;
    unsigned offm = 0, onm = 0;
#pragma unroll
    for (int j = 0; j < NV; j++) {
        const float4 g4 = gr[j];
        const float4 t4 = tr[j];
        const int4   o4 = off[j];
        const int4   n4 = on[j];
        sg += (g4.x + g4.y) + (g4.z + g4.w);
        st += (t4.x + t4.y) + (t4.z + t4.w);
        const int s = 4 * j;
        offm |= ((unsigned)o4.x << s) | ((unsigned)o4.y << (s + 1))
              | ((unsigned)o4.z << (s + 2)) | ((unsigned)o4.w << (s + 3));
        onm  |= ((unsigned)n4.x << s) | ((unsigned)n4.y << (s + 1))
              | ((unsigned)n4.z << (s + 2)) | ((unsigned)n4.w << (s + 3));
    }
    const int osum = __popc(offm);

    // ---- warp-level: inclusive scan of osum, reduce sg/st ----
    int incl = osum;
#pragma unroll
    for (int d = 1; d < 32; d <<= 1) {
        int v = __shfl_up_sync(FULLM, incl, d);
        if (lane >= d) incl += v;
    }
#pragma unroll
    for (int d = 16; d > 0; d >>= 1) {
        sg += __shfl_down_sync(FULLM, sg, d);
        st += __shfl_down_sync(FULLM, st, d);
    }
    if (lane == 31) s_wosum[wid] = incl;
    if (lane == 0) { s_wg[wid] = sg; s_wt[wid] = st; }
    __syncthreads();

    // ---- cross-warp prefix + scatter onset counts ----
    int wpre = 0;
#pragma unroll
    for (int w = 0; w < 8; w++) wpre += (w < wid) ? s_wosum[w] : 0;
    const int excl = wpre + incl - osum;   // exclusive offset-prefix of this thread

    unsigned m = onm;
    if (tid == 0) m &= ~1u;                // reference masks onsets at idx==0
    while (m) {
        const int j = __ffs(m) - 1;
        m &= m - 1;
        const int seg = excl + __popc(offm & ((2u << j) - 1u));  // inclusive cumsum at l
        if (seg < NMAX) atomicAdd(&s_counts[seg], 1);
    }
    __syncthreads();

    // ---- per-note loss, block reduce ----
    int   n_notes = 0;
    float tg = 0.f, tt = 0.f;
#pragma unroll
    for (int w = 0; w < 8; w++) { n_notes += s_wosum[w]; tg += s_wg[w]; tt += s_wt[w]; }
    const float dd = (tg - tt) * (1.0f / LEN);

    float val = 0.f;
    if (tid < NMAX) {
        float c = -(float)s_counts[tid];
        if (tid == 0) c -= (float)(offm & 1u);   // tid0's chunk holds offsets[b,0]
        if (tid >= n_notes) c = 0.f;
        const float diff = fabsf(c * dd / (c + 1e-6f));
        val = fmaxf(diff - 0.5f, 0.f);
    }
#pragma unroll
    for (int d = 16; d > 0; d >>= 1) val += __shfl_down_sync(FULLM, val, d);
    if (lane == 0 && wid < 4) s_red[wid] = val;   // warps 0-3 hold tid<128
    __syncthreads();

    // ---- single packed atomic: count in high bits, fixed-point sum in low ----
    if (tid == 0) {
        const float bs = (s_red[0] + s_red[1]) + (s_red[2] + s_red[3]);
        const unsigned long long q =
            (unsigned long long)__float2ll_rn(bs * FP_SCALE);
        const unsigned long long add = (1ULL << CNT_SHIFT) + q;
        const unsigned long long old = atomicAdd(&g_pack, add);
        if ((old >> CNT_SHIFT) == (unsigned long long)(BATCH - 1)) {
            const unsigned long long tot = (old + add) & VAL_MASK;
            out[0] = (float)((double)tot * (1.0 / (double)FP_SCALE)
                              * (1.0 / (NMAX * BATCH)));
            g_pack = 0ULL;   // all 64 adds landed (count==64): safe to rearm
        }
    }
}

extern "C" void kernel_launch(void* const* d_in, const int* in_sizes, int n_in,
                              void* d_out, int out_size)
{
    const float* gen_f0   = (const float*)d_in[0];
    const float* contours = (const float*)d_in[1];
    const int*   onsets   = (const int*)d_in[2];
    const int*   offsets  = (const int*)d_in[3];
    // d_in[4] = n_notes_max (compile-time NMAX=128 for this shape)

    pitch_fused_kernel<<<BATCH, T1>>>(gen_f0, contours, onsets, offsets, (float*)d_out);
}